// round 2
// baseline (speedup 1.0000x reference)
#include <cuda_runtime.h>
#include <math.h>

#define BB 4
#define NSEQ 2048
#define DIN 513
#define NH 8
#define DH 64
#define MTOT (BB*NSEQ)            // 8192
#define INVK 10.0f
#define KCURV 0.1f
#define EPSF 1e-9f
#define SCL 0.125f                // 1/sqrt(64)

// ---------------- scratch (device globals; no runtime allocation) ----------
__device__ float g_qs[BB*NH*NSEQ*DH];
__device__ float g_ks[BB*NH*NSEQ*DH];
__device__ float g_vs[BB*NH*NSEQ*DH];
__device__ float g_qt[BB*NH*NSEQ];
__device__ float g_kt[BB*NH*NSEQ];
__device__ float g_vt[BB*NH*NSEQ];
__device__ float g_cat[(size_t)MTOT*DIN];   // [B*N, 513]: [t', space_cat]
__device__ float g_rowsq[MTOT];

// ---------------------------------------------------------------------------
// Kernel 0: zero the per-row sumsq accumulator
// ---------------------------------------------------------------------------
__global__ void zero_rowsq_kernel() {
    int i = blockIdx.x * blockDim.x + threadIdx.x;
    if (i < MTOT) g_rowsq[i] = 0.f;
}

// ---------------------------------------------------------------------------
// Kernel 1: per-head Lorentz projections.
//   space = x @ W[h] + b[h]   (GEMM M=8192, K=513, N=64)
//   t = sqrt(max(1/k + ||space||^2, eps))
// grid = (M/64, H, 3)   block = (16,16)
// ---------------------------------------------------------------------------
__global__ void proj_kernel(const float* __restrict__ x,
                            const float* __restrict__ Wq, const float* __restrict__ bq,
                            const float* __restrict__ Wk, const float* __restrict__ bk,
                            const float* __restrict__ Wv, const float* __restrict__ bv) {
    __shared__ float As[64][33];
    __shared__ float Bs[32][65];
    __shared__ float rs[64];

    const int h    = blockIdx.y;
    const int row0 = blockIdx.x * 64;
    const int tx = threadIdx.x, ty = threadIdx.y;
    const int tid = ty * 16 + tx;

    const float* W;  const float* bias;  float* outs;  float* outt;
    if (blockIdx.z == 0)      { W = Wq; bias = bq; outs = g_qs; outt = g_qt; }
    else if (blockIdx.z == 1) { W = Wk; bias = bk; outs = g_ks; outt = g_kt; }
    else                      { W = Wv; bias = bv; outs = g_vs; outt = g_vt; }

    const float* Wh = W + (size_t)h * DIN * DH;

    float acc[4][4] = {};

    for (int k0 = 0; k0 < DIN; k0 += 32) {
        // load A tile 64x32
        #pragma unroll
        for (int i = 0; i < 8; i++) {
            int idx = tid + i * 256;
            int r = idx >> 5, c = idx & 31;
            int k = k0 + c;
            As[r][c] = (k < DIN) ? x[(size_t)(row0 + r) * DIN + k] : 0.f;
        }
        // load B tile 32x64
        #pragma unroll
        for (int i = 0; i < 8; i++) {
            int idx = tid + i * 256;
            int kk = idx >> 6, m = idx & 63;
            int k = k0 + kk;
            Bs[kk][m] = (k < DIN) ? Wh[(size_t)k * DH + m] : 0.f;
        }
        __syncthreads();
        #pragma unroll
        for (int kk = 0; kk < 32; kk++) {
            float a[4], bb[4];
            #pragma unroll
            for (int i = 0; i < 4; i++) a[i] = As[ty * 4 + i][kk];
            #pragma unroll
            for (int j = 0; j < 4; j++) bb[j] = Bs[kk][tx * 4 + j];
            #pragma unroll
            for (int i = 0; i < 4; i++)
                #pragma unroll
                for (int j = 0; j < 4; j++)
                    acc[i][j] = fmaf(a[i], bb[j], acc[i][j]);
        }
        __syncthreads();
    }

    // epilogue: bias + per-row sumsq (block owns full dh=64 row)
    if (tid < 64) rs[tid] = 0.f;
    __syncthreads();

    float val[4][4];
    #pragma unroll
    for (int i = 0; i < 4; i++) {
        float p = 0.f;
        #pragma unroll
        for (int j = 0; j < 4; j++) {
            val[i][j] = acc[i][j] + bias[h * DH + tx * 4 + j];
            p += val[i][j] * val[i][j];
        }
        atomicAdd(&rs[ty * 4 + i], p);
    }
    __syncthreads();

    const int b  = row0 / NSEQ;
    const int n0 = row0 % NSEQ;
    const size_t base = ((size_t)(b * NH + h) * NSEQ + n0);
    #pragma unroll
    for (int i = 0; i < 4; i++) {
        int r = ty * 4 + i;
        #pragma unroll
        for (int j = 0; j < 4; j++)
            outs[(base + r) * DH + tx * 4 + j] = val[i][j];
    }
    if (tid < 64)
        outt[base + tid] = sqrtf(fmaxf(INVK + rs[tid], EPSF));
}

// ---------------------------------------------------------------------------
// Kernel 2: flash-style Lorentz attention + midpoint normalization.
//   scores = (q_s.k_s - q_t k_t) * SCL ; softmax (online) ; s = P @ [v_t, v_s]
//   out_space = s_s * rsqrt(max(k*(s_t^2 - ||s_s||^2), eps)) -> g_cat[:,1+h*64+ :]
// grid = (N/64, B*H)  block = (16,16)  dynamic smem.
// ---------------------------------------------------------------------------
#define ATTN_SMEM_FLOATS (3*64*65 + 6*64 + 64*16)
#define ATTN_SMEM_BYTES  (ATTN_SMEM_FLOATS*4)

__global__ void attn_kernel() {
    extern __shared__ float sm[];
    float* Qs   = sm;                 // 64*65
    float* Ks   = Qs + 64 * 65;       // 64*65 (aliased as P after S compute)
    float* Vs   = Ks + 64 * 65;       // 64*65
    float* Ps   = Ks;                 // alias
    float* qts  = Vs + 64 * 65;       // 64
    float* kts  = qts + 64;
    float* vts  = kts + 64;
    float* mrow = vts + 64;
    float* lrow = mrow + 64;
    float* frow = lrow + 64;
    float* red  = frow + 64;          // 64*16

    const int bh = blockIdx.y;
    const int r0 = blockIdx.x * 64;
    const int tx = threadIdx.x, ty = threadIdx.y;
    const int tid = ty * 16 + tx;

    const float* qsp = g_qs + (size_t)bh * NSEQ * DH;
    const float* ksp = g_ks + (size_t)bh * NSEQ * DH;
    const float* vsp = g_vs + (size_t)bh * NSEQ * DH;

    // load Q tile + stats init
    #pragma unroll
    for (int i = 0; i < 16; i++) {
        int idx = tid + i * 256;
        int r = idx >> 6, d = idx & 63;
        Qs[r * 65 + d] = qsp[(size_t)(r0 + r) * DH + d];
    }
    if (tid < 64) {
        qts[tid]  = g_qt[(size_t)bh * NSEQ + r0 + tid];
        mrow[tid] = -1e30f;
        lrow[tid] = 0.f;
    }

    float O[4][4] = {};
    float Otp[4]  = {};

    for (int j0 = 0; j0 < NSEQ; j0 += 64) {
        __syncthreads();    // protect Ks/Vs/red reuse from previous iteration
        #pragma unroll
        for (int i = 0; i < 16; i++) {
            int idx = tid + i * 256;
            int c = idx >> 6, d = idx & 63;
            Ks[c * 65 + d] = ksp[(size_t)(j0 + c) * DH + d];
            Vs[c * 65 + d] = vsp[(size_t)(j0 + c) * DH + d];
        }
        if (tid < 64) {
            kts[tid] = g_kt[(size_t)bh * NSEQ + j0 + tid];
            vts[tid] = g_vt[(size_t)bh * NSEQ + j0 + tid];
        }
        __syncthreads();

        // S = Qs . Ks^T (spatial part)
        float S[4][4] = {};
        #pragma unroll
        for (int kk = 0; kk < 64; kk++) {
            float a[4], bb[4];
            #pragma unroll
            for (int i = 0; i < 4; i++) a[i] = Qs[(ty * 4 + i) * 65 + kk];
            #pragma unroll
            for (int j = 0; j < 4; j++) bb[j] = Ks[(tx * 4 + j) * 65 + kk];
            #pragma unroll
            for (int i = 0; i < 4; i++)
                #pragma unroll
                for (int j = 0; j < 4; j++)
                    S[i][j] = fmaf(a[i], bb[j], S[i][j]);
        }
        // finish score, tile row-max
        #pragma unroll
        for (int i = 0; i < 4; i++) {
            int r = ty * 4 + i;
            float qt = qts[r];
            float pm = -1e30f;
            #pragma unroll
            for (int j = 0; j < 4; j++) {
                int c = tx * 4 + j;
                S[i][j] = (S[i][j] - qt * kts[c]) * SCL;
                pm = fmaxf(pm, S[i][j]);
            }
            red[r * 16 + tx] = pm;
        }
        __syncthreads();
        if (tid < 64) {
            float mx = red[tid * 16];
            #pragma unroll
            for (int t = 1; t < 16; t++) mx = fmaxf(mx, red[tid * 16 + t]);
            float mo = mrow[tid];
            float mn = fmaxf(mo, mx);
            float f  = __expf(mo - mn);
            mrow[tid] = mn;
            frow[tid] = f;
            lrow[tid] *= f;
        }
        __syncthreads();
        // P = exp(S - m), partial row sums, rescale accumulators
        #pragma unroll
        for (int i = 0; i < 4; i++) {
            int r = ty * 4 + i;
            float mr = mrow[r];
            float f  = frow[r];
            float ps = 0.f;
            #pragma unroll
            for (int j = 0; j < 4; j++) {
                float p = __expf(S[i][j] - mr);
                Ps[r * 65 + tx * 4 + j] = p;
                ps += p;
                O[i][j] *= f;
            }
            Otp[i] *= f;
            red[r * 16 + tx] = ps;
        }
        __syncthreads();
        if (tid < 64) {
            float s = 0.f;
            #pragma unroll
            for (int t = 0; t < 16; t++) s += red[tid * 16 + t];
            lrow[tid] += s;
        }
        // O += P @ Vs (spatial)
        #pragma unroll
        for (int kk = 0; kk < 64; kk++) {
            float p[4], v[4];
            #pragma unroll
            for (int i = 0; i < 4; i++) p[i] = Ps[(ty * 4 + i) * 65 + kk];
            #pragma unroll
            for (int j = 0; j < 4; j++) v[j] = Vs[kk * 65 + tx * 4 + j];
            #pragma unroll
            for (int i = 0; i < 4; i++)
                #pragma unroll
                for (int j = 0; j < 4; j++)
                    O[i][j] = fmaf(p[i], v[j], O[i][j]);
        }
        // time-column partial (each tx covers kk in [tx*4, tx*4+4))
        #pragma unroll
        for (int t = 0; t < 4; t++) {
            int kk = tx * 4 + t;
            float vt = vts[kk];
            #pragma unroll
            for (int i = 0; i < 4; i++)
                Otp[i] = fmaf(Ps[(ty * 4 + i) * 65 + kk], vt, Otp[i]);
        }
    }
    __syncthreads();

    // reduce time column across tx
    #pragma unroll
    for (int i = 0; i < 4; i++) red[(ty * 4 + i) * 16 + tx] = Otp[i];
    __syncthreads();
    if (tid < 64) {
        float s = 0.f;
        #pragma unroll
        for (int t = 0; t < 16; t++) s += red[tid * 16 + t];
        mrow[tid] = s / lrow[tid];     // s_t (reuse mrow)
    }
    __syncthreads();

    // finalize: s = O/l ; row sumsq of spatial part
    #pragma unroll
    for (int i = 0; i < 4; i++) {
        int r = ty * 4 + i;
        float linv = 1.f / lrow[r];
        float pss = 0.f;
        #pragma unroll
        for (int j = 0; j < 4; j++) {
            O[i][j] *= linv;
            pss += O[i][j] * O[i][j];
        }
        red[r * 16 + tx] = pss;
    }
    __syncthreads();
    if (tid < 64) {
        float ss = 0.f;
        #pragma unroll
        for (int t = 0; t < 16; t++) ss += red[tid * 16 + t];
        float st = mrow[tid];
        frow[tid] = rsqrtf(fmaxf(KCURV * (st * st - ss), EPSF));
    }
    __syncthreads();

    // write normalized spatial part into concat layout g_cat[row][1 + h*64 + c]
    const int b = bh / NH, h = bh % NH;
    #pragma unroll
    for (int i = 0; i < 4; i++) {
        int r = ty * 4 + i;
        size_t rowg = (size_t)b * NSEQ + r0 + r;
        float fac = frow[r];
        #pragma unroll
        for (int j = 0; j < 4; j++)
            g_cat[rowg * DIN + 1 + h * DH + tx * 4 + j] = O[i][j] * fac;
    }
}

// ---------------------------------------------------------------------------
// Kernel 3: t' = sqrt(max(1/k + ||space_cat||^2, eps)) -> g_cat[row][0]
// ---------------------------------------------------------------------------
__global__ void cat_time_kernel() {
    __shared__ float red[128];
    const int row = blockIdx.x;
    const float* p = g_cat + (size_t)row * DIN + 1;
    float s = 0.f;
    for (int i = threadIdx.x; i < 512; i += 128) {
        float v = p[i];
        s += v * v;
    }
    red[threadIdx.x] = s;
    __syncthreads();
    for (int off = 64; off > 0; off >>= 1) {
        if (threadIdx.x < off) red[threadIdx.x] += red[threadIdx.x + off];
        __syncthreads();
    }
    if (threadIdx.x == 0)
        g_cat[(size_t)row * DIN] = sqrtf(fmaxf(INVK + red[0], EPSF));
}

// ---------------------------------------------------------------------------
// Kernel 4: output FC GEMM: o_space = cat513 @ Wo + bo  (M=8192,K=513,N=512)
//   writes spatial part into d_out[row*513 + 1 + col] and per-row sumsq.
// grid = (M/64, 512/64)  block = (16,16)
// ---------------------------------------------------------------------------
__global__ void out_gemm_kernel(const float* __restrict__ Wo,
                                const float* __restrict__ bo,
                                float* __restrict__ out) {
    __shared__ float As[64][33];
    __shared__ float Bs[32][65];
    __shared__ float rs[64];

    const int ct   = blockIdx.y * 64;
    const int row0 = blockIdx.x * 64;
    const int tx = threadIdx.x, ty = threadIdx.y;
    const int tid = ty * 16 + tx;

    float acc[4][4] = {};

    for (int k0 = 0; k0 < DIN; k0 += 32) {
        #pragma unroll
        for (int i = 0; i < 8; i++) {
            int idx = tid + i * 256;
            int r = idx >> 5, c = idx & 31;
            int k = k0 + c;
            As[r][c] = (k < DIN) ? g_cat[(size_t)(row0 + r) * DIN + k] : 0.f;
        }
        #pragma unroll
        for (int i = 0; i < 8; i++) {
            int idx = tid + i * 256;
            int kk = idx >> 6, m = idx & 63;
            int k = k0 + kk;
            Bs[kk][m] = (k < DIN) ? Wo[(size_t)k * 512 + ct + m] : 0.f;
        }
        __syncthreads();
        #pragma unroll
        for (int kk = 0; kk < 32; kk++) {
            float a[4], bb[4];
            #pragma unroll
            for (int i = 0; i < 4; i++) a[i] = As[ty * 4 + i][kk];
            #pragma unroll
            for (int j = 0; j < 4; j++) bb[j] = Bs[kk][tx * 4 + j];
            #pragma unroll
            for (int i = 0; i < 4; i++)
                #pragma unroll
                for (int j = 0; j < 4; j++)
                    acc[i][j] = fmaf(a[i], bb[j], acc[i][j]);
        }
        __syncthreads();
    }

    if (tid < 64) rs[tid] = 0.f;
    __syncthreads();

    #pragma unroll
    for (int i = 0; i < 4; i++) {
        int r = ty * 4 + i;
        float p = 0.f;
        #pragma unroll
        for (int j = 0; j < 4; j++) {
            float v = acc[i][j] + bo[ct + tx * 4 + j];
            out[(size_t)(row0 + r) * DIN + 1 + ct + tx * 4 + j] = v;
            p += v * v;
        }
        atomicAdd(&rs[r], p);
    }
    __syncthreads();
    if (tid < 64)
        atomicAdd(&g_rowsq[row0 + tid], rs[tid]);
}

// ---------------------------------------------------------------------------
// Kernel 5: final Lorentz time column
// ---------------------------------------------------------------------------
__global__ void final_time_kernel(float* __restrict__ out) {
    int row = blockIdx.x * blockDim.x + threadIdx.x;
    if (row < MTOT)
        out[(size_t)row * DIN] = sqrtf(fmaxf(INVK + g_rowsq[row], EPSF));
}

// ---------------------------------------------------------------------------
extern "C" void kernel_launch(void* const* d_in, const int* in_sizes, int n_in,
                              void* d_out, int out_size) {
    const float* x  = (const float*)d_in[0];
    const float* Wq = (const float*)d_in[1];
    const float* bq = (const float*)d_in[2];
    const float* Wk = (const float*)d_in[3];
    const float* bk = (const float*)d_in[4];
    const float* Wv = (const float*)d_in[5];
    const float* bv = (const float*)d_in[6];
    const float* Wo = (const float*)d_in[7];
    const float* bo = (const float*)d_in[8];
    float* out = (float*)d_out;

    cudaFuncSetAttribute(attn_kernel,
                         cudaFuncAttributeMaxDynamicSharedMemorySize,
                         ATTN_SMEM_BYTES);

    dim3 blk(16, 16);

    zero_rowsq_kernel<<<(MTOT + 255) / 256, 256>>>();
    proj_kernel<<<dim3(MTOT / 64, NH, 3), blk>>>(x, Wq, bq, Wk, bk, Wv, bv);
    attn_kernel<<<dim3(NSEQ / 64, BB * NH), blk, ATTN_SMEM_BYTES>>>();
    cat_time_kernel<<<MTOT, 128>>>();
    out_gemm_kernel<<<dim3(MTOT / 64, 512 / 64), blk>>>(Wo, bo, out);
    final_time_kernel<<<(MTOT + 255) / 256, 256>>>(out);
}

// round 3
// speedup vs baseline: 1.0007x; 1.0007x over previous
#include <cuda_runtime.h>
#include <math.h>

#define BB 4
#define NSEQ 2048
#define DIN 513
#define NH 8
#define DH 64
#define MTOT (BB*NSEQ)            // 8192
#define INVK 10.0f
#define KCURV 0.1f
#define EPSF 1e-9f
#define SCL 0.125f                // 1/sqrt(64)

// ---------------- scratch (device globals; no runtime allocation) ----------
__device__ float g_qs[BB*NH*NSEQ*DH];
__device__ float g_ks[BB*NH*NSEQ*DH];
__device__ float g_vs[BB*NH*NSEQ*DH];
__device__ float g_qt[BB*NH*NSEQ];
__device__ float g_kt[BB*NH*NSEQ];
__device__ float g_vt[BB*NH*NSEQ];
__device__ float g_cat[(size_t)MTOT*DIN];   // [B*N, 513]: [t', space_cat]
__device__ float g_rowsq[MTOT];

// ---------------------------------------------------------------------------
// Kernel 0: zero the per-row sumsq accumulator
// ---------------------------------------------------------------------------
__global__ void zero_rowsq_kernel() {
    int i = blockIdx.x * blockDim.x + threadIdx.x;
    if (i < MTOT) g_rowsq[i] = 0.f;
}

// ---------------------------------------------------------------------------
// Kernel 1: per-head Lorentz projections.
//   space = x @ W[h] + b[h]   (GEMM M=8192, K=513, N=64)
//   t = sqrt(max(1/k + ||space||^2, eps))
// grid = (M/64, H, 3)   block = (16,16)
// ---------------------------------------------------------------------------
__global__ void proj_kernel(const float* __restrict__ x,
                            const float* __restrict__ Wq, const float* __restrict__ bq,
                            const float* __restrict__ Wk, const float* __restrict__ bk,
                            const float* __restrict__ Wv, const float* __restrict__ bv) {
    __shared__ float As[64][33];
    __shared__ float Bs[32][65];
    __shared__ float rs[64];

    const int h    = blockIdx.y;
    const int row0 = blockIdx.x * 64;
    const int tx = threadIdx.x, ty = threadIdx.y;
    const int tid = ty * 16 + tx;

    const float* W;  const float* bias;  float* outs;  float* outt;
    if (blockIdx.z == 0)      { W = Wq; bias = bq; outs = g_qs; outt = g_qt; }
    else if (blockIdx.z == 1) { W = Wk; bias = bk; outs = g_ks; outt = g_kt; }
    else                      { W = Wv; bias = bv; outs = g_vs; outt = g_vt; }

    const float* Wh = W + (size_t)h * DIN * DH;

    float acc[4][4] = {};

    for (int k0 = 0; k0 < DIN; k0 += 32) {
        // load A tile 64x32
        #pragma unroll
        for (int i = 0; i < 8; i++) {
            int idx = tid + i * 256;
            int r = idx >> 5, c = idx & 31;
            int k = k0 + c;
            As[r][c] = (k < DIN) ? x[(size_t)(row0 + r) * DIN + k] : 0.f;
        }
        // load B tile 32x64
        #pragma unroll
        for (int i = 0; i < 8; i++) {
            int idx = tid + i * 256;
            int kk = idx >> 6, m = idx & 63;
            int k = k0 + kk;
            Bs[kk][m] = (k < DIN) ? Wh[(size_t)k * DH + m] : 0.f;
        }
        __syncthreads();
        #pragma unroll
        for (int kk = 0; kk < 32; kk++) {
            float a[4], bb[4];
            #pragma unroll
            for (int i = 0; i < 4; i++) a[i] = As[ty * 4 + i][kk];
            #pragma unroll
            for (int j = 0; j < 4; j++) bb[j] = Bs[kk][tx * 4 + j];
            #pragma unroll
            for (int i = 0; i < 4; i++)
                #pragma unroll
                for (int j = 0; j < 4; j++)
                    acc[i][j] = fmaf(a[i], bb[j], acc[i][j]);
        }
        __syncthreads();
    }

    // epilogue: bias + per-row sumsq (block owns full dh=64 row)
    if (tid < 64) rs[tid] = 0.f;
    __syncthreads();

    float val[4][4];
    #pragma unroll
    for (int i = 0; i < 4; i++) {
        float p = 0.f;
        #pragma unroll
        for (int j = 0; j < 4; j++) {
            val[i][j] = acc[i][j] + bias[h * DH + tx * 4 + j];
            p += val[i][j] * val[i][j];
        }
        atomicAdd(&rs[ty * 4 + i], p);
    }
    __syncthreads();

    const int b  = row0 / NSEQ;
    const int n0 = row0 % NSEQ;
    const size_t base = ((size_t)(b * NH + h) * NSEQ + n0);
    #pragma unroll
    for (int i = 0; i < 4; i++) {
        int r = ty * 4 + i;
        #pragma unroll
        for (int j = 0; j < 4; j++)
            outs[(base + r) * DH + tx * 4 + j] = val[i][j];
    }
    if (tid < 64)
        outt[base + tid] = sqrtf(fmaxf(INVK + rs[tid], EPSF));
}

// ---------------------------------------------------------------------------
// Kernel 2: flash-style Lorentz attention + midpoint normalization.
//   scores = (q_s.k_s - q_t k_t) * SCL ; softmax (online) ; s = P @ [v_t, v_s]
//   out_space = s_s * rsqrt(max(k*(s_t^2 - ||s_s||^2), eps)) -> g_cat[:,1+h*64+ :]
// grid = (N/64, B*H)  block = (16,16)  dynamic smem.
// ---------------------------------------------------------------------------
#define ATTN_SMEM_FLOATS (3*64*65 + 6*64 + 64*16)
#define ATTN_SMEM_BYTES  (ATTN_SMEM_FLOATS*4)

__global__ void attn_kernel() {
    extern __shared__ float sm[];
    float* Qs   = sm;                 // 64*65
    float* Ks   = Qs + 64 * 65;       // 64*65 (aliased as P after S compute)
    float* Vs   = Ks + 64 * 65;       // 64*65
    float* Ps   = Ks;                 // alias
    float* qts  = Vs + 64 * 65;       // 64
    float* kts  = qts + 64;
    float* vts  = kts + 64;
    float* mrow = vts + 64;
    float* lrow = mrow + 64;
    float* frow = lrow + 64;
    float* red  = frow + 64;          // 64*16

    const int bh = blockIdx.y;
    const int r0 = blockIdx.x * 64;
    const int tx = threadIdx.x, ty = threadIdx.y;
    const int tid = ty * 16 + tx;

    const float* qsp = g_qs + (size_t)bh * NSEQ * DH;
    const float* ksp = g_ks + (size_t)bh * NSEQ * DH;
    const float* vsp = g_vs + (size_t)bh * NSEQ * DH;

    // load Q tile + stats init
    #pragma unroll
    for (int i = 0; i < 16; i++) {
        int idx = tid + i * 256;
        int r = idx >> 6, d = idx & 63;
        Qs[r * 65 + d] = qsp[(size_t)(r0 + r) * DH + d];
    }
    if (tid < 64) {
        qts[tid]  = g_qt[(size_t)bh * NSEQ + r0 + tid];
        mrow[tid] = -1e30f;
        lrow[tid] = 0.f;
    }

    float O[4][4] = {};
    float Otp[4]  = {};

    for (int j0 = 0; j0 < NSEQ; j0 += 64) {
        __syncthreads();    // protect Ks/Vs/red reuse from previous iteration
        #pragma unroll
        for (int i = 0; i < 16; i++) {
            int idx = tid + i * 256;
            int c = idx >> 6, d = idx & 63;
            Ks[c * 65 + d] = ksp[(size_t)(j0 + c) * DH + d];
            Vs[c * 65 + d] = vsp[(size_t)(j0 + c) * DH + d];
        }
        if (tid < 64) {
            kts[tid] = g_kt[(size_t)bh * NSEQ + j0 + tid];
            vts[tid] = g_vt[(size_t)bh * NSEQ + j0 + tid];
        }
        __syncthreads();

        // S = Qs . Ks^T (spatial part)
        float S[4][4] = {};
        #pragma unroll
        for (int kk = 0; kk < 64; kk++) {
            float a[4], bb[4];
            #pragma unroll
            for (int i = 0; i < 4; i++) a[i] = Qs[(ty * 4 + i) * 65 + kk];
            #pragma unroll
            for (int j = 0; j < 4; j++) bb[j] = Ks[(tx * 4 + j) * 65 + kk];
            #pragma unroll
            for (int i = 0; i < 4; i++)
                #pragma unroll
                for (int j = 0; j < 4; j++)
                    S[i][j] = fmaf(a[i], bb[j], S[i][j]);
        }
        // finish score, tile row-max
        #pragma unroll
        for (int i = 0; i < 4; i++) {
            int r = ty * 4 + i;
            float qt = qts[r];
            float pm = -1e30f;
            #pragma unroll
            for (int j = 0; j < 4; j++) {
                int c = tx * 4 + j;
                S[i][j] = (S[i][j] - qt * kts[c]) * SCL;
                pm = fmaxf(pm, S[i][j]);
            }
            red[r * 16 + tx] = pm;
        }
        __syncthreads();
        if (tid < 64) {
            float mx = red[tid * 16];
            #pragma unroll
            for (int t = 1; t < 16; t++) mx = fmaxf(mx, red[tid * 16 + t]);
            float mo = mrow[tid];
            float mn = fmaxf(mo, mx);
            float f  = __expf(mo - mn);
            mrow[tid] = mn;
            frow[tid] = f;
            lrow[tid] *= f;
        }
        __syncthreads();
        // P = exp(S - m), partial row sums, rescale accumulators
        #pragma unroll
        for (int i = 0; i < 4; i++) {
            int r = ty * 4 + i;
            float mr = mrow[r];
            float f  = frow[r];
            float ps = 0.f;
            #pragma unroll
            for (int j = 0; j < 4; j++) {
                float p = __expf(S[i][j] - mr);
                Ps[r * 65 + tx * 4 + j] = p;
                ps += p;
                O[i][j] *= f;
            }
            Otp[i] *= f;
            red[r * 16 + tx] = ps;
        }
        __syncthreads();
        if (tid < 64) {
            float s = 0.f;
            #pragma unroll
            for (int t = 0; t < 16; t++) s += red[tid * 16 + t];
            lrow[tid] += s;
        }
        // O += P @ Vs (spatial)
        #pragma unroll
        for (int kk = 0; kk < 64; kk++) {
            float p[4], v[4];
            #pragma unroll
            for (int i = 0; i < 4; i++) p[i] = Ps[(ty * 4 + i) * 65 + kk];
            #pragma unroll
            for (int j = 0; j < 4; j++) v[j] = Vs[kk * 65 + tx * 4 + j];
            #pragma unroll
            for (int i = 0; i < 4; i++)
                #pragma unroll
                for (int j = 0; j < 4; j++)
                    O[i][j] = fmaf(p[i], v[j], O[i][j]);
        }
        // time-column partial (each tx covers kk in [tx*4, tx*4+4))
        #pragma unroll
        for (int t = 0; t < 4; t++) {
            int kk = tx * 4 + t;
            float vt = vts[kk];
            #pragma unroll
            for (int i = 0; i < 4; i++)
                Otp[i] = fmaf(Ps[(ty * 4 + i) * 65 + kk], vt, Otp[i]);
        }
    }
    __syncthreads();

    // reduce time column across tx
    #pragma unroll
    for (int i = 0; i < 4; i++) red[(ty * 4 + i) * 16 + tx] = Otp[i];
    __syncthreads();
    if (tid < 64) {
        float s = 0.f;
        #pragma unroll
        for (int t = 0; t < 16; t++) s += red[tid * 16 + t];
        mrow[tid] = s / lrow[tid];     // s_t (reuse mrow)
    }
    __syncthreads();

    // finalize: s = O/l ; row sumsq of spatial part
    #pragma unroll
    for (int i = 0; i < 4; i++) {
        int r = ty * 4 + i;
        float linv = 1.f / lrow[r];
        float pss = 0.f;
        #pragma unroll
        for (int j = 0; j < 4; j++) {
            O[i][j] *= linv;
            pss += O[i][j] * O[i][j];
        }
        red[r * 16 + tx] = pss;
    }
    __syncthreads();
    if (tid < 64) {
        float ss = 0.f;
        #pragma unroll
        for (int t = 0; t < 16; t++) ss += red[tid * 16 + t];
        float st = mrow[tid];
        frow[tid] = rsqrtf(fmaxf(KCURV * (st * st - ss), EPSF));
    }
    __syncthreads();

    // write normalized spatial part into concat layout g_cat[row][1 + h*64 + c]
    const int b = bh / NH, h = bh % NH;
    #pragma unroll
    for (int i = 0; i < 4; i++) {
        int r = ty * 4 + i;
        size_t rowg = (size_t)b * NSEQ + r0 + r;
        float fac = frow[r];
        #pragma unroll
        for (int j = 0; j < 4; j++)
            g_cat[rowg * DIN + 1 + h * DH + tx * 4 + j] = O[i][j] * fac;
    }
}

// ---------------------------------------------------------------------------
// Kernel 3: t' = sqrt(max(1/k + ||space_cat||^2, eps)) -> g_cat[row][0]
// ---------------------------------------------------------------------------
__global__ void cat_time_kernel() {
    __shared__ float red[128];
    const int row = blockIdx.x;
    const float* p = g_cat + (size_t)row * DIN + 1;
    float s = 0.f;
    for (int i = threadIdx.x; i < 512; i += 128) {
        float v = p[i];
        s += v * v;
    }
    red[threadIdx.x] = s;
    __syncthreads();
    for (int off = 64; off > 0; off >>= 1) {
        if (threadIdx.x < off) red[threadIdx.x] += red[threadIdx.x + off];
        __syncthreads();
    }
    if (threadIdx.x == 0)
        g_cat[(size_t)row * DIN] = sqrtf(fmaxf(INVK + red[0], EPSF));
}

// ---------------------------------------------------------------------------
// Kernel 4: output FC GEMM: o_space = cat513 @ Wo + bo  (M=8192,K=513,N=512)
//   writes spatial part into d_out[row*513 + 1 + col] and per-row sumsq.
// grid = (M/64, 512/64)  block = (16,16)
// ---------------------------------------------------------------------------
__global__ void out_gemm_kernel(const float* __restrict__ Wo,
                                const float* __restrict__ bo,
                                float* __restrict__ out) {
    __shared__ float As[64][33];
    __shared__ float Bs[32][65];
    __shared__ float rs[64];

    const int ct   = blockIdx.y * 64;
    const int row0 = blockIdx.x * 64;
    const int tx = threadIdx.x, ty = threadIdx.y;
    const int tid = ty * 16 + tx;

    float acc[4][4] = {};

    for (int k0 = 0; k0 < DIN; k0 += 32) {
        #pragma unroll
        for (int i = 0; i < 8; i++) {
            int idx = tid + i * 256;
            int r = idx >> 5, c = idx & 31;
            int k = k0 + c;
            As[r][c] = (k < DIN) ? g_cat[(size_t)(row0 + r) * DIN + k] : 0.f;
        }
        #pragma unroll
        for (int i = 0; i < 8; i++) {
            int idx = tid + i * 256;
            int kk = idx >> 6, m = idx & 63;
            int k = k0 + kk;
            Bs[kk][m] = (k < DIN) ? Wo[(size_t)k * 512 + ct + m] : 0.f;
        }
        __syncthreads();
        #pragma unroll
        for (int kk = 0; kk < 32; kk++) {
            float a[4], bb[4];
            #pragma unroll
            for (int i = 0; i < 4; i++) a[i] = As[ty * 4 + i][kk];
            #pragma unroll
            for (int j = 0; j < 4; j++) bb[j] = Bs[kk][tx * 4 + j];
            #pragma unroll
            for (int i = 0; i < 4; i++)
                #pragma unroll
                for (int j = 0; j < 4; j++)
                    acc[i][j] = fmaf(a[i], bb[j], acc[i][j]);
        }
        __syncthreads();
    }

    if (tid < 64) rs[tid] = 0.f;
    __syncthreads();

    #pragma unroll
    for (int i = 0; i < 4; i++) {
        int r = ty * 4 + i;
        float p = 0.f;
        #pragma unroll
        for (int j = 0; j < 4; j++) {
            float v = acc[i][j] + bo[ct + tx * 4 + j];
            out[(size_t)(row0 + r) * DIN + 1 + ct + tx * 4 + j] = v;
            p += v * v;
        }
        atomicAdd(&rs[r], p);
    }
    __syncthreads();
    if (tid < 64)
        atomicAdd(&g_rowsq[row0 + tid], rs[tid]);
}

// ---------------------------------------------------------------------------
// Kernel 5: final Lorentz time column
// ---------------------------------------------------------------------------
__global__ void final_time_kernel(float* __restrict__ out) {
    int row = blockIdx.x * blockDim.x + threadIdx.x;
    if (row < MTOT)
        out[(size_t)row * DIN] = sqrtf(fmaxf(INVK + g_rowsq[row], EPSF));
}

// ---------------------------------------------------------------------------
extern "C" void kernel_launch(void* const* d_in, const int* in_sizes, int n_in,
                              void* d_out, int out_size) {
    const float* x  = (const float*)d_in[0];
    const float* Wq = (const float*)d_in[1];
    const float* bq = (const float*)d_in[2];
    const float* Wk = (const float*)d_in[3];
    const float* bk = (const float*)d_in[4];
    const float* Wv = (const float*)d_in[5];
    const float* bv = (const float*)d_in[6];
    const float* Wo = (const float*)d_in[7];
    const float* bo = (const float*)d_in[8];
    float* out = (float*)d_out;

    cudaFuncSetAttribute(attn_kernel,
                         cudaFuncAttributeMaxDynamicSharedMemorySize,
                         ATTN_SMEM_BYTES);

    dim3 blk(16, 16);

    zero_rowsq_kernel<<<(MTOT + 255) / 256, 256>>>();
    proj_kernel<<<dim3(MTOT / 64, NH, 3), blk>>>(x, Wq, bq, Wk, bk, Wv, bv);
    attn_kernel<<<dim3(NSEQ / 64, BB * NH), blk, ATTN_SMEM_BYTES>>>();
    cat_time_kernel<<<MTOT, 128>>>();
    out_gemm_kernel<<<dim3(MTOT / 64, 512 / 64), blk>>>(Wo, bo, out);
    final_time_kernel<<<(MTOT + 255) / 256, 256>>>(out);
}

// round 10
// speedup vs baseline: 1.2138x; 1.2130x over previous
#include <cuda_runtime.h>
#include <math.h>
#include <stdint.h>

#define BB 4
#define NSEQ 2048
#define DIN 513
#define NH 8
#define DH 64
#define MTOT (BB*NSEQ)
#define INVK 10.0f
#define KCURV 0.1f
#define EPSF 1e-9f
#define SCL 0.125f

__device__ float g_qs[BB*NH*NSEQ*DH];
__device__ float g_ks[BB*NH*NSEQ*DH];
__device__ float g_vs[BB*NH*NSEQ*DH];
__device__ float g_qt[BB*NH*NSEQ];
__device__ float g_kt[BB*NH*NSEQ];
__device__ float g_vt[BB*NH*NSEQ];
__device__ float g_cat[(size_t)MTOT*DIN];
__device__ float g_rowsq[MTOT];

// ============================ helpers ======================================
__device__ __forceinline__ uint32_t f2tf32(float f) {
    uint32_t r; asm("cvt.rna.tf32.f32 %0, %1;" : "=r"(r) : "f"(f)); return r;
}
__device__ __forceinline__ float uf(uint32_t u) { return __uint_as_float(u); }
__device__ __forceinline__ void split_tf32(float x, uint32_t& hi, uint32_t& lo) {
    hi = f2tf32(x);
    lo = f2tf32(x - __uint_as_float(hi));
}
// mma.sync m16n8k8 tf32: D += A*B  (baseline sm_80+ instruction, no 'a' feature)
#define MMA(d, a, b0, b1)                                                     \
    asm volatile("mma.sync.aligned.m16n8k8.row.col.f32.tf32.tf32.f32 "        \
        "{%0,%1,%2,%3}, {%4,%5,%6,%7}, {%8,%9}, {%0,%1,%2,%3};"               \
        : "+f"((d)[0]), "+f"((d)[1]), "+f"((d)[2]), "+f"((d)[3])              \
        : "r"((a)[0]), "r"((a)[1]), "r"((a)[2]), "r"((a)[3]),                 \
          "r"(b0), "r"(b1))

// smem strides (words) chosen for conflict-free fragment loads
#define KST 68
#define VST 72

// ---------------------------------------------------------------------------
__global__ void zero_rowsq_kernel() {
    int i = blockIdx.x * blockDim.x + threadIdx.x;
    if (i < MTOT) g_rowsq[i] = 0.f;
}

// ---------------------------------------------------------------------------
// Kernel 1: per-head Lorentz projections (scalar GEMM, known-good)
// ---------------------------------------------------------------------------
__global__ void proj_kernel(const float* __restrict__ x,
                            const float* __restrict__ Wq, const float* __restrict__ bq,
                            const float* __restrict__ Wk, const float* __restrict__ bk,
                            const float* __restrict__ Wv, const float* __restrict__ bv) {
    __shared__ float As[64][33];
    __shared__ float Bs[32][65];
    __shared__ float rs[64];

    const int h    = blockIdx.y;
    const int row0 = blockIdx.x * 64;
    const int tx = threadIdx.x, ty = threadIdx.y;
    const int tid = ty * 16 + tx;

    const float* W;  const float* bias;  float* outs;  float* outt;
    if (blockIdx.z == 0)      { W = Wq; bias = bq; outs = g_qs; outt = g_qt; }
    else if (blockIdx.z == 1) { W = Wk; bias = bk; outs = g_ks; outt = g_kt; }
    else                      { W = Wv; bias = bv; outs = g_vs; outt = g_vt; }

    const float* Wh = W + (size_t)h * DIN * DH;
    float acc[4][4] = {};

    for (int k0 = 0; k0 < DIN; k0 += 32) {
        #pragma unroll
        for (int i = 0; i < 8; i++) {
            int idx = tid + i * 256;
            int r = idx >> 5, c = idx & 31;
            int k = k0 + c;
            As[r][c] = (k < DIN) ? x[(size_t)(row0 + r) * DIN + k] : 0.f;
        }
        #pragma unroll
        for (int i = 0; i < 8; i++) {
            int idx = tid + i * 256;
            int kk = idx >> 6, m = idx & 63;
            int k = k0 + kk;
            Bs[kk][m] = (k < DIN) ? Wh[(size_t)k * DH + m] : 0.f;
        }
        __syncthreads();
        #pragma unroll
        for (int kk = 0; kk < 32; kk++) {
            float a[4], bb[4];
            #pragma unroll
            for (int i = 0; i < 4; i++) a[i] = As[ty * 4 + i][kk];
            #pragma unroll
            for (int j = 0; j < 4; j++) bb[j] = Bs[kk][tx * 4 + j];
            #pragma unroll
            for (int i = 0; i < 4; i++)
                #pragma unroll
                for (int j = 0; j < 4; j++)
                    acc[i][j] = fmaf(a[i], bb[j], acc[i][j]);
        }
        __syncthreads();
    }

    if (tid < 64) rs[tid] = 0.f;
    __syncthreads();

    float val[4][4];
    #pragma unroll
    for (int i = 0; i < 4; i++) {
        float p = 0.f;
        #pragma unroll
        for (int j = 0; j < 4; j++) {
            val[i][j] = acc[i][j] + bias[h * DH + tx * 4 + j];
            p += val[i][j] * val[i][j];
        }
        atomicAdd(&rs[ty * 4 + i], p);
    }
    __syncthreads();

    const int b  = row0 / NSEQ;
    const int n0 = row0 % NSEQ;
    const size_t base = ((size_t)(b * NH + h) * NSEQ + n0);
    #pragma unroll
    for (int i = 0; i < 4; i++) {
        int r = ty * 4 + i;
        #pragma unroll
        for (int j = 0; j < 4; j++)
            outs[(base + r) * DH + tx * 4 + j] = val[i][j];
    }
    if (tid < 64)
        outt[base + tid] = sqrtf(fmaxf(INVK + rs[tid], EPSF));
}

// ---------------------------------------------------------------------------
// Kernel 2: mma.sync tf32 (3xTF32) flash attention, no-max softmax.
// grid = (NSEQ/64, B*H), 128 threads (4 warps x m16). O accumulates in regs.
// ---------------------------------------------------------------------------
#define ATT_SMEM_FLOATS (4*64*KST + 2*64*VST + 128)
#define ATT_SMEM_BYTES  (ATT_SMEM_FLOATS*4)

__global__ void __launch_bounds__(128) attn_mma_kernel() {
    extern __shared__ float sm[];
    float* sPh = sm;                    // 64 x KST : P hi (also Q staging)
    float* sPl = sPh + 64 * KST;        // 64 x KST : P lo
    float* sKh = sPl + 64 * KST;        // 64 x KST : K hi  [key][d]
    float* sKl = sKh + 64 * KST;
    float* sVh = sKl + 64 * KST;        // 64 x VST : V hi  [key][d]
    float* sVl = sVh + 64 * VST;
    float* skt = sVl + 64 * VST;        // 64
    float* svt = skt + 64;              // 64

    const int tid  = threadIdx.x;
    const int lane = tid & 31;
    const int w    = tid >> 5;
    const int q    = lane & 3;          // quad index (k / col-pair)
    const int r    = lane >> 2;         // row-in-group / n index
    const int bh   = blockIdx.y;
    const int r0   = blockIdx.x * 64;
    const int wr   = w * 16;            // warp's first q-row (local)

    const float* qsp = g_qs + ((size_t)bh * NSEQ + r0) * DH;
    const float* ksp = g_ks + (size_t)bh * NSEQ * DH;
    const float* vsp = g_vs + (size_t)bh * NSEQ * DH;

    // ---- stage Q (raw fp32) into sPh, then build resident tf32 fragments --
    #pragma unroll
    for (int i = 0; i < 8; i++) {
        int idx = tid + i * 128;
        int row = idx >> 4, c4 = idx & 15;
        *(float4*)&sPh[row * KST + c4 * 4] =
            *(const float4*)(qsp + row * 64 + c4 * 4);
    }
    __syncthreads();

    uint32_t qh[8][4], ql[8][4];
    const int arow = wr + r;
    #pragma unroll
    for (int s = 0; s < 8; s++) {
        float a0 = sPh[arow * KST + s * 8 + q];
        float a1 = sPh[(arow + 8) * KST + s * 8 + q];
        float a2 = sPh[arow * KST + s * 8 + q + 4];
        float a3 = sPh[(arow + 8) * KST + s * 8 + q + 4];
        split_tf32(a0, qh[s][0], ql[s][0]);
        split_tf32(a1, qh[s][1], ql[s][1]);
        split_tf32(a2, qh[s][2], ql[s][2]);
        split_tf32(a3, qh[s][3], ql[s][3]);
    }
    const float qtr0 = g_qt[(size_t)bh * NSEQ + r0 + arow];
    const float qtr8 = g_qt[(size_t)bh * NSEQ + r0 + arow + 8];

    float O[8][4] = {};
    float l0 = 0.f, l8 = 0.f, lt0 = 0.f, lt8 = 0.f;

    for (int t = 0; t < NSEQ / 64; t++) {
        __syncthreads();   // all warps done with previous K/V tiles
        const int j0 = t * 64;
        #pragma unroll
        for (int i = 0; i < 8; i++) {
            int idx = tid + i * 128;
            int row = idx >> 4, c4 = idx & 15;
            float4 kv = *(const float4*)(ksp + (size_t)(j0 + row) * 64 + c4 * 4);
            float4 vv = *(const float4*)(vsp + (size_t)(j0 + row) * 64 + c4 * 4);
            uint32_t h0,h1,h2,h3, e0,e1,e2,e3;
            split_tf32(kv.x, h0, e0); split_tf32(kv.y, h1, e1);
            split_tf32(kv.z, h2, e2); split_tf32(kv.w, h3, e3);
            *(float4*)&sKh[row * KST + c4 * 4] = make_float4(uf(h0),uf(h1),uf(h2),uf(h3));
            *(float4*)&sKl[row * KST + c4 * 4] = make_float4(uf(e0),uf(e1),uf(e2),uf(e3));
            split_tf32(vv.x, h0, e0); split_tf32(vv.y, h1, e1);
            split_tf32(vv.z, h2, e2); split_tf32(vv.w, h3, e3);
            *(float4*)&sVh[row * VST + c4 * 4] = make_float4(uf(h0),uf(h1),uf(h2),uf(h3));
            *(float4*)&sVl[row * VST + c4 * 4] = make_float4(uf(e0),uf(e1),uf(e2),uf(e3));
        }
        if (tid < 64) {
            skt[tid] = g_kt[(size_t)bh * NSEQ + j0 + tid];
            svt[tid] = g_vt[(size_t)bh * NSEQ + j0 + tid];
        }
        __syncthreads();

        // ---- S = Q.K^T (3xTF32) ----
        float C[8][4] = {};
        #pragma unroll
        for (int s = 0; s < 8; s++) {
            #pragma unroll
            for (int n = 0; n < 8; n++) {
                int bb = (n * 8 + r) * KST + s * 8 + q;
                uint32_t bh0 = __float_as_uint(sKh[bb]);
                uint32_t bh1 = __float_as_uint(sKh[bb + 4]);
                uint32_t bl0 = __float_as_uint(sKl[bb]);
                uint32_t bl1 = __float_as_uint(sKl[bb + 4]);
                MMA(C[n], qh[s], bh0, bh1);
                MMA(C[n], ql[s], bh0, bh1);
                MMA(C[n], qh[s], bl0, bl1);
            }
        }

        // ---- softmax (no max), P -> smem as tf32 hi/lo ----
        const int prow = wr + r;
        #pragma unroll
        for (int n = 0; n < 8; n++) {
            int col0 = n * 8 + 2 * q;
            float2 kt2 = *(float2*)&skt[col0];
            float2 vt2 = *(float2*)&svt[col0];
            float p00 = __expf((C[n][0] - qtr0 * kt2.x) * SCL);
            float p01 = __expf((C[n][1] - qtr0 * kt2.y) * SCL);
            float p10 = __expf((C[n][2] - qtr8 * kt2.x) * SCL);
            float p11 = __expf((C[n][3] - qtr8 * kt2.y) * SCL);
            l0 += p00 + p01;  l8 += p10 + p11;
            lt0 += p00 * vt2.x + p01 * vt2.y;
            lt8 += p10 * vt2.x + p11 * vt2.y;
            uint32_t h00,h01,h10,h11, e00,e01,e10,e11;
            split_tf32(p00, h00, e00); split_tf32(p01, h01, e01);
            split_tf32(p10, h10, e10); split_tf32(p11, h11, e11);
            *(float2*)&sPh[prow * KST + col0]       = make_float2(uf(h00), uf(h01));
            *(float2*)&sPh[(prow + 8) * KST + col0] = make_float2(uf(h10), uf(h11));
            *(float2*)&sPl[prow * KST + col0]       = make_float2(uf(e00), uf(e01));
            *(float2*)&sPl[(prow + 8) * KST + col0] = make_float2(uf(e10), uf(e11));
        }
        __syncwarp();   // P is warp-local (own 16 rows)

        // ---- O += P.V (3xTF32) ----
        #pragma unroll
        for (int s = 0; s < 8; s++) {
            int ab = arow * KST + s * 8 + q;
            uint32_t pa[4], pl_[4];
            pa[0] = __float_as_uint(sPh[ab]);
            pa[1] = __float_as_uint(sPh[ab + 8 * KST]);
            pa[2] = __float_as_uint(sPh[ab + 4]);
            pa[3] = __float_as_uint(sPh[ab + 8 * KST + 4]);
            pl_[0] = __float_as_uint(sPl[ab]);
            pl_[1] = __float_as_uint(sPl[ab + 8 * KST]);
            pl_[2] = __float_as_uint(sPl[ab + 4]);
            pl_[3] = __float_as_uint(sPl[ab + 8 * KST + 4]);
            #pragma unroll
            for (int n = 0; n < 8; n++) {
                int vb = (s * 8 + q) * VST + n * 8 + r;
                uint32_t vh0 = __float_as_uint(sVh[vb]);
                uint32_t vh1 = __float_as_uint(sVh[vb + 4 * VST]);
                uint32_t vl0 = __float_as_uint(sVl[vb]);
                uint32_t vl1 = __float_as_uint(sVl[vb + 4 * VST]);
                MMA(O[n], pa,  vh0, vh1);
                MMA(O[n], pl_, vh0, vh1);
                MMA(O[n], pa,  vl0, vl1);
            }
        }
    }

    // ---- epilogue: quad-reduce l/lt, normalize, midpoint, write g_cat ----
    l0  += __shfl_xor_sync(0xffffffffu, l0, 1);  l0  += __shfl_xor_sync(0xffffffffu, l0, 2);
    l8  += __shfl_xor_sync(0xffffffffu, l8, 1);  l8  += __shfl_xor_sync(0xffffffffu, l8, 2);
    lt0 += __shfl_xor_sync(0xffffffffu, lt0, 1); lt0 += __shfl_xor_sync(0xffffffffu, lt0, 2);
    lt8 += __shfl_xor_sync(0xffffffffu, lt8, 1); lt8 += __shfl_xor_sync(0xffffffffu, lt8, 2);

    const float li0 = 1.f / l0, li8 = 1.f / l8;
    const float st0 = lt0 * li0, st8 = lt8 * li8;
    float ss0 = 0.f, ss8 = 0.f;
    #pragma unroll
    for (int n = 0; n < 8; n++) {
        O[n][0] *= li0; O[n][1] *= li0;
        O[n][2] *= li8; O[n][3] *= li8;
        ss0 += O[n][0] * O[n][0] + O[n][1] * O[n][1];
        ss8 += O[n][2] * O[n][2] + O[n][3] * O[n][3];
    }
    ss0 += __shfl_xor_sync(0xffffffffu, ss0, 1); ss0 += __shfl_xor_sync(0xffffffffu, ss0, 2);
    ss8 += __shfl_xor_sync(0xffffffffu, ss8, 1); ss8 += __shfl_xor_sync(0xffffffffu, ss8, 2);

    const float fac0 = rsqrtf(fmaxf(KCURV * (st0 * st0 - ss0), EPSF));
    const float fac8 = rsqrtf(fmaxf(KCURV * (st8 * st8 - ss8), EPSF));

    const int b = bh / NH, h = bh % NH;
    float* d0 = g_cat + ((size_t)b * NSEQ + r0 + arow)     * DIN + 1 + h * DH;
    float* d8 = g_cat + ((size_t)b * NSEQ + r0 + arow + 8) * DIN + 1 + h * DH;
    #pragma unroll
    for (int n = 0; n < 8; n++) {
        int col0 = n * 8 + 2 * q;
        d0[col0]     = O[n][0] * fac0;
        d0[col0 + 1] = O[n][1] * fac0;
        d8[col0]     = O[n][2] * fac8;
        d8[col0 + 1] = O[n][3] * fac8;
    }
}

// ---------------------------------------------------------------------------
// Kernel 3: t' = sqrt(max(1/k + ||space_cat||^2, eps))
// ---------------------------------------------------------------------------
__global__ void cat_time_kernel() {
    __shared__ float red[128];
    const int row = blockIdx.x;
    const float* p = g_cat + (size_t)row * DIN + 1;
    float s = 0.f;
    for (int i = threadIdx.x; i < 512; i += 128) {
        float v = p[i];
        s += v * v;
    }
    red[threadIdx.x] = s;
    __syncthreads();
    for (int off = 64; off > 0; off >>= 1) {
        if (threadIdx.x < off) red[threadIdx.x] += red[threadIdx.x + off];
        __syncthreads();
    }
    if (threadIdx.x == 0)
        g_cat[(size_t)row * DIN] = sqrtf(fmaxf(INVK + red[0], EPSF));
}

// ---------------------------------------------------------------------------
// Kernel 4: output FC GEMM (scalar, known-good)
// ---------------------------------------------------------------------------
__global__ void out_gemm_kernel(const float* __restrict__ Wo,
                                const float* __restrict__ bo,
                                float* __restrict__ out) {
    __shared__ float As[64][33];
    __shared__ float Bs[32][65];
    __shared__ float rs[64];

    const int ct   = blockIdx.y * 64;
    const int row0 = blockIdx.x * 64;
    const int tx = threadIdx.x, ty = threadIdx.y;
    const int tid = ty * 16 + tx;

    float acc[4][4] = {};

    for (int k0 = 0; k0 < DIN; k0 += 32) {
        #pragma unroll
        for (int i = 0; i < 8; i++) {
            int idx = tid + i * 256;
            int r = idx >> 5, c = idx & 31;
            int k = k0 + c;
            As[r][c] = (k < DIN) ? g_cat[(size_t)(row0 + r) * DIN + k] : 0.f;
        }
        #pragma unroll
        for (int i = 0; i < 8; i++) {
            int idx = tid + i * 256;
            int kk = idx >> 6, m = idx & 63;
            int k = k0 + kk;
            Bs[kk][m] = (k < DIN) ? Wo[(size_t)k * 512 + ct + m] : 0.f;
        }
        __syncthreads();
        #pragma unroll
        for (int kk = 0; kk < 32; kk++) {
            float a[4], bb[4];
            #pragma unroll
            for (int i = 0; i < 4; i++) a[i] = As[ty * 4 + i][kk];
            #pragma unroll
            for (int j = 0; j < 4; j++) bb[j] = Bs[kk][tx * 4 + j];
            #pragma unroll
            for (int i = 0; i < 4; i++)
                #pragma unroll
                for (int j = 0; j < 4; j++)
                    acc[i][j] = fmaf(a[i], bb[j], acc[i][j]);
        }
        __syncthreads();
    }

    if (tid < 64) rs[tid] = 0.f;
    __syncthreads();

    #pragma unroll
    for (int i = 0; i < 4; i++) {
        int r = ty * 4 + i;
        float p = 0.f;
        #pragma unroll
        for (int j = 0; j < 4; j++) {
            float v = acc[i][j] + bo[ct + tx * 4 + j];
            out[(size_t)(row0 + r) * DIN + 1 + ct + tx * 4 + j] = v;
            p += v * v;
        }
        atomicAdd(&rs[r], p);
    }
    __syncthreads();
    if (tid < 64)
        atomicAdd(&g_rowsq[row0 + tid], rs[tid]);
}

// ---------------------------------------------------------------------------
__global__ void final_time_kernel(float* __restrict__ out) {
    int row = blockIdx.x * blockDim.x + threadIdx.x;
    if (row < MTOT)
        out[(size_t)row * DIN] = sqrtf(fmaxf(INVK + g_rowsq[row], EPSF));
}

// ---------------------------------------------------------------------------
extern "C" void kernel_launch(void* const* d_in, const int* in_sizes, int n_in,
                              void* d_out, int out_size) {
    const float* x  = (const float*)d_in[0];
    const float* Wq = (const float*)d_in[1];
    const float* bq = (const float*)d_in[2];
    const float* Wk = (const float*)d_in[3];
    const float* bk = (const float*)d_in[4];
    const float* Wv = (const float*)d_in[5];
    const float* bv = (const float*)d_in[6];
    const float* Wo = (const float*)d_in[7];
    const float* bo = (const float*)d_in[8];
    float* out = (float*)d_out;

    cudaFuncSetAttribute(attn_mma_kernel,
                         cudaFuncAttributeMaxDynamicSharedMemorySize,
                         ATT_SMEM_BYTES);

    dim3 blk(16, 16);

    zero_rowsq_kernel<<<(MTOT + 255) / 256, 256>>>();
    proj_kernel<<<dim3(MTOT / 64, NH, 3), blk>>>(x, Wq, bq, Wk, bk, Wv, bv);
    attn_mma_kernel<<<dim3(NSEQ / 64, BB * NH), 128, ATT_SMEM_BYTES>>>();
    cat_time_kernel<<<MTOT, 128>>>();
    out_gemm_kernel<<<dim3(MTOT / 64, 512 / 64), blk>>>(Wo, bo, out);
    final_time_kernel<<<(MTOT + 255) / 256, 256>>>(out);
}